// round 15
// baseline (speedup 1.0000x reference)
#include <cuda_runtime.h>

// Problem constants (NonMaxSuppression: B=16, C=80, N=5000)
#define NB      16
#define NC      80
#define NN      5000
#define MAXOUT  100
#define NBC     (NB * NC)          // 1280
#define NT      256                // threads per CTA
#define HB      2048               // counting-sort buckets (11 bits of ~score)
#define KCAP    1024               // key slots per band
#define WBAND   640                // target candidates per band (>> ~130 needed)
#define PREF_K  256                // walk prefetch chunk (== NT)
#define OUT_ROWS (NBC * MAXOUT)    // 128000
#define OUT_ELEMS (OUT_ROWS * 3)   // 384000

// Dynamic smem (bytes): key(8192) + cur(8192) + pref(4096) = 20480 -> 6 CTAs/SM
#define OFF_KEY  0                          // u64[KCAP]
#define OFF_CUR  (KCAP * 8)                 // int[HB]
#define OFF_PREF (OFF_CUR + HB * 4)         // float4[PREF_K]
#define DYNSZ    (OFF_PREF + PREF_K * 16)   // 20480 B (< 48KB default, no attribute)

// Cross-kernel scratch (device globals: the sanctioned no-alloc scratch)
__device__ int g_sel[OUT_ROWS];
__device__ int g_cnt[NBC];
__device__ int g_off[NBC];

// Bucket from score bits (score in (0.5,1) => bits in [0x3F000001,0x3F7FFFFF]).
// ~bits ascends where score descends; top 11 bits give the bucket. Clamped.
__device__ __forceinline__ int score_bucket_bits(unsigned int bits)
{
    int bkt = (int)((~bits) >> 12) - 0xC0800;
    bkt = bkt < 0 ? 0 : (bkt > (HB - 1) ? (HB - 1) : bkt);
    return bkt;
}

// ---------------------------------------------------------------------------
// Kernel 1: per-(b,c) NMS. Histogram + scan over ALL kept scores (exact
// cumulative counts), then band-wise: scatter+sort only the top ~WBAND keys
// (u64 key = (~score_bits<<32)|idx; ascending == (score desc, idx asc) ==
// exact greedy order), walk them with one warp. If the walk needs more, the
// next band resumes using the preserved absolute cursors of unprocessed
// buckets — exact for any data, single band in practice.
// ---------------------------------------------------------------------------
__global__ __launch_bounds__(NT, 6)
void nms_kernel(const float* __restrict__ boxes, const float* __restrict__ scores)
{
    extern __shared__ unsigned char dyn[];
    unsigned long long* s_key = (unsigned long long*)(dyn + OFF_KEY);
    int*    s_cur  = (int*)(dyn + OFF_CUR);
    float4* s_pref = (float4*)(dyn + OFF_PREF);

    __shared__ int s_wsum[8];
    __shared__ int s_total, s_S, s_cutb, s_p1;

    const int bc   = blockIdx.x;
    const int b    = bc / NC;
    const int tid  = threadIdx.x;
    const int lane = tid & 31;
    const int wid  = tid >> 5;

    const float*  sc_row = scores + (size_t)bc * NN;
    const float4* bx_row = (const float4*)boxes + (size_t)b * NN;

    // ---- zero histogram ----
    for (int h = tid; h < HB; h += NT) s_cur[h] = 0;
    if (tid == 0) s_S = 0;
    __syncthreads();

    // ---- histogram of kept scores (coalesced gmem read #1) ----
    for (int i = tid; i < NN; i += NT) {
        float s = sc_row[i];
        if (s > 0.5f)
            atomicAdd(&s_cur[score_bucket_bits(__float_as_uint(s))], 1);
    }
    __syncthreads();

    // ---- exclusive prefix over HB buckets (8 contiguous/thread) ----
    int loc[8];
    int lsum = 0;
#pragma unroll
    for (int j = 0; j < 8; j++) { loc[j] = s_cur[tid * 8 + j]; lsum += loc[j]; }
    int pv = lsum;
#pragma unroll
    for (int o = 1; o < 32; o <<= 1) {
        int n = __shfl_up_sync(0xffffffffu, pv, o);
        if (lane >= o) pv += n;
    }
    if (lane == 31) s_wsum[wid] = pv;
    __syncthreads();
    if (tid == 0) {
        int acc = 0;
#pragma unroll
        for (int w = 0; w < 8; w++) { int x = s_wsum[w]; s_wsum[w] = acc; acc += x; }
    }
    __syncthreads();
    int bkbase = (pv - lsum) + s_wsum[wid];
#pragma unroll
    for (int j = 0; j < 8; j++) { s_cur[tid * 8 + j] = bkbase; bkbase += loc[j]; }
    if (tid == NT - 1) s_total = bkbase;
    __syncthreads();
    const int total = s_total;

    // ---- walk-selected-set registers (used by warp 0) ----
    float sx1[4], sy1[4], sx2[4], sy2[4], sar[4];
#pragma unroll
    for (int t = 0; t < 4; t++) { sx1[t]=0.f; sy1[t]=0.f; sx2[t]=0.f; sy2[t]=0.f; sar[t]=0.f; }

    int p0 = 0;        // absolute keys processed so far
    int bcur = 0;      // first unprocessed bucket
    while (true) {
        if (s_S >= MAXOUT || p0 >= total) break;      // uniform (post-barrier)

        // ---- find cut bucket: smallest h with start(h) >= p0 + WBAND ----
        if (tid == 0) s_cutb = HB;
        __syncthreads();
#pragma unroll
        for (int j = 0; j < 8; j++) {
            int h = tid * 8 + j;
            if (h >= bcur && s_cur[h] >= p0 + WBAND) atomicMin(&s_cutb, h);
        }
        __syncthreads();
        int cutb = s_cutb;
        if (tid == 0) s_p1 = (cutb < HB) ? s_cur[cutb] : total;
        __syncthreads();
        int p1 = s_p1;
        int bandn = p1 - p0;
        if (bandn > KCAP) bandn = KCAP;               // pathological clamp

        // ---- scatter band keys (gmem read #2; L1/L2 resident) ----
        for (int i = tid; i < NN; i += NT) {
            float s = sc_row[i];
            if (s > 0.5f) {
                unsigned int bits = __float_as_uint(s);
                int bkt = score_bucket_bits(bits);
                if (bkt >= bcur && bkt < cutb) {
                    int pos = atomicAdd(&s_cur[bkt], 1) - p0;
                    if (pos < KCAP)
                        s_key[pos] = ((unsigned long long)(~bits) << 32) | (unsigned int)i;
                }
            }
        }
        __syncthreads();

        // ---- per-bucket insertion sort within the band (ascending u64) ----
#pragma unroll
        for (int j = 0; j < 8; j++) {
            int h = tid * 8 + j;
            if (h >= bcur && h < cutb) {
                int s0 = ((h == bcur) ? p0 : s_cur[h - 1]) - p0;   // end(h-1)=start(h)
                int s1 = s_cur[h] - p0;
                if (s1 > KCAP) s1 = KCAP;
                for (int i2 = s0 + 1; i2 < s1; i2++) {
                    unsigned long long key = s_key[i2];
                    int j2 = i2 - 1;
                    while (j2 >= s0 && s_key[j2] > key) { s_key[j2 + 1] = s_key[j2]; j2--; }
                    s_key[j2 + 1] = key;
                }
            }
        }
        __syncthreads();

        // ---- chunked prefetch + single-warp greedy walk over the band ----
        int chunk_start = 0;
        while (true) {
            int S0 = s_S;                             // uniform (post-barrier)
            if (chunk_start >= bandn || S0 >= MAXOUT) break;
            int chunk_end = chunk_start + PREF_K;
            if (chunk_end > bandn) chunk_end = bandn;

            int p = chunk_start + tid;
            if (p < chunk_end)
                s_pref[tid] = bx_row[(unsigned int)s_key[p]];   // low word = idx
            __syncthreads();

            if (wid == 0) {
                int S = S0;
                int n = chunk_end - chunk_start;
                float4 nb = s_pref[0];                 // software pipeline
                for (int q = 0; q < n && S < MAXOUT; ++q) {
                    float4 cb = nb;
                    if (q + 1 < n) nb = s_pref[q + 1]; // LDS off critical path
                    float ca = (cb.z - cb.x) * (cb.w - cb.y);
                    int tmax = S >> 5;                 // warp-uniform slot bound
                    int sup = 0;
#pragma unroll
                    for (int t = 0; t < 4; t++) {
                        if (t > tmax) break;
                        bool valid = (t * 32 + lane) < S;
                        float ix1 = fmaxf(sx1[t], cb.x);
                        float iy1 = fmaxf(sy1[t], cb.y);
                        float ix2 = fminf(sx2[t], cb.z);
                        float iy2 = fminf(sy2[t], cb.w);
                        float w   = fmaxf(ix2 - ix1, 0.f);
                        float h   = fmaxf(iy2 - iy1, 0.f);
                        float inter = w * h;
                        // Bit-exact reference compare (validated rel_err==0.0):
                        // suppress iff rn(inter / rn(rn(ca+sar)-inter)) > 0.5
                        //   <=> inter - 0.5*U > U*2^-25 (exact in deciding band)
                        float tt = ca + sar[t];
                        float U  = tt - inter;
                        float d  = inter - 0.5f * U;
                        float lo = U * 2.9802322387695312e-8f;
                        if (valid && d > lo) sup = 1;
                    }
                    if (__ballot_sync(0xffffffffu, sup)) continue;
                    if (lane == (S & 31)) {
                        int t = S >> 5;
                        if      (t == 0) { sx1[0]=cb.x; sy1[0]=cb.y; sx2[0]=cb.z; sy2[0]=cb.w; sar[0]=ca; }
                        else if (t == 1) { sx1[1]=cb.x; sy1[1]=cb.y; sx2[1]=cb.z; sy2[1]=cb.w; sar[1]=ca; }
                        else if (t == 2) { sx1[2]=cb.x; sy1[2]=cb.y; sx2[2]=cb.z; sy2[2]=cb.w; sar[2]=ca; }
                        else             { sx1[3]=cb.x; sy1[3]=cb.y; sx2[3]=cb.z; sy2[3]=cb.w; sar[3]=ca; }
                    }
                    if (lane == 0)
                        g_sel[bc * MAXOUT + S] = (int)(unsigned int)s_key[chunk_start + q];
                    S++;
                }
                if (lane == 0) s_S = S;
            }
            __syncthreads();
            chunk_start = chunk_end;
        }

        p0 = p1;
        bcur = cutb;
    }
    if (tid == 0) g_cnt[bc] = s_S;
}

// ---------------------------------------------------------------------------
// Kernel 2: exclusive prefix scan of the 1280 per-row counts (one tiny block)
// ---------------------------------------------------------------------------
__global__ __launch_bounds__(NT)
void scan_kernel()
{
    __shared__ int s_w[8];
    int tid = threadIdx.x, lane = tid & 31, wid = tid >> 5;
    int c[5];
    int sum = 0;
#pragma unroll
    for (int j = 0; j < 5; j++) { c[j] = g_cnt[tid * 5 + j]; sum += c[j]; }
    int v = sum;
#pragma unroll
    for (int o = 1; o < 32; o <<= 1) {
        int n = __shfl_up_sync(0xffffffffu, v, o);
        if (lane >= o) v += n;
    }
    if (lane == 31) s_w[wid] = v;
    __syncthreads();
    if (tid == 0) {
        int acc = 0;
#pragma unroll
        for (int w = 0; w < 8; w++) { int x = s_w[w]; s_w[w] = acc; acc += x; }
    }
    __syncthreads();
    int base = (v - sum) + s_w[wid];
#pragma unroll
    for (int j = 0; j < 5; j++) { g_off[tid * 5 + j] = base; base += c[j]; }
}

// ---------------------------------------------------------------------------
// Kernel 3: fused pack. Packed region [0, 3T) written only by the scatter;
// tail [3T, lim) only by the zero loop — disjoint. Triples as FLOAT values
// (output buffer is compared as float32; all values exact in fp32).
// ---------------------------------------------------------------------------
__global__ __launch_bounds__(NT)
void pack_kernel(float* __restrict__ out, int out_elems)
{
    int i = blockIdx.x * blockDim.x + threadIdx.x;   // over OUT_ROWS
    int lim = out_elems < OUT_ELEMS ? out_elems : OUT_ELEMS;
    int T = g_off[NBC - 1] + g_cnt[NBC - 1];         // total packed triples

    if (i < OUT_ROWS) {
        int bc = i / MAXOUT;
        int k  = i - bc * MAXOUT;
        if (k < g_cnt[bc]) {
            int d = g_off[bc] + k;
            if (3 * d + 2 < lim) {
                out[3 * d + 0] = (float)(bc / NC);
                out[3 * d + 1] = (float)(bc % NC);
                out[3 * d + 2] = (float)g_sel[i];
            }
        }
    }
    // tail zeros (grid-stride over [3T, lim))
    for (int z = 3 * T + i; z < lim; z += OUT_ROWS) out[z] = 0.0f;
}

// ---------------------------------------------------------------------------
extern "C" void kernel_launch(void* const* d_in, const int* in_sizes, int n_in,
                              void* d_out, int out_size)
{
    // Identify buffers by RELATIVE size: scores (6.4M elems) >> boxes (320k).
    const float* boxes  = (const float*)d_in[0];
    const float* scores = (const float*)d_in[1];
    if (n_in >= 2 && in_sizes[0] > in_sizes[1]) {
        scores = (const float*)d_in[0];
        boxes  = (const float*)d_in[1];
    }
    float* out = (float*)d_out;

    nms_kernel<<<NBC, NT, DYNSZ>>>(boxes, scores);   // 20KB dyn smem (<48KB default)
    scan_kernel<<<1, NT>>>();
    pack_kernel<<<(OUT_ROWS + NT - 1) / NT, NT>>>(out, out_size);
}

// round 16
// speedup vs baseline: 1.1921x; 1.1921x over previous
#include <cuda_runtime.h>

// Problem constants (NonMaxSuppression: B=16, C=80, N=5000)
#define NB      16
#define NC      80
#define NN      5000
#define MAXOUT  100
#define NBC     (NB * NC)          // 1280
#define NT      256                // threads per CTA
#define PER     20                 // ceil(NN / NT) scores per thread (registers)
#define HB      1024               // counting-sort buckets (10 bits of ~score)
#define KSEL    512                // top-K band target (walk needs ~130)
#define KCAP    640                // key slots (K + max bucket overshoot)
#define PREF_K  256                // walk prefetch chunk (== NT)
#define OUT_ROWS (NBC * MAXOUT)    // 128000
#define OUT_ELEMS (OUT_ROWS * 3)   // 384000

// Dynamic smem (bytes): key(5120) + cur(4096) + pref(4096) = 13312 (<48KB)
#define OFF_KEY  0                          // u64[KCAP]
#define OFF_CUR  (KCAP * 8)                 // int[HB]
#define OFF_PREF (OFF_CUR + HB * 4)         // float4[PREF_K]
#define DYNSZ    (OFF_PREF + PREF_K * 16)

// Cross-kernel scratch (device globals: the sanctioned no-alloc scratch)
__device__ int g_sel[OUT_ROWS];
__device__ int g_cnt[NBC];
__device__ int g_off[NBC];

// Bucket from score bits (score in (0.5,1) => bits in [0x3F000001,0x3F7FFFFF]).
// ~bits ascends where score descends; top 10 bits give the bucket. Clamped.
__device__ __forceinline__ int score_bucket_bits(unsigned int bits)
{
    int bkt = (int)((~bits) >> 13) - 0x60400;
    bkt = bkt < 0 ? 0 : (bkt > (HB - 1) ? (HB - 1) : bkt);
    return bkt;
}

// ---------------------------------------------------------------------------
// Kernel 1: per-(b,c) NMS. Scores staged in registers (ONE gmem pass).
// Full histogram + scan give exact cumulative counts; only the top-K band's
// keys are scattered & sorted (u64 key = (~score_bits<<32)|idx; ascending ==
// (score desc, idx asc) == exact greedy order incl. tie-breaks). Single-warp
// walk; if it exhausts a band with <100 keeps (virtually impossible), the
// band loop re-scatters the next band FROM REGISTERS using the preserved
// absolute cursors of unprocessed buckets — exact for any data.
// ---------------------------------------------------------------------------
__global__ __launch_bounds__(NT, 5)
void nms_kernel(const float* __restrict__ boxes, const float* __restrict__ scores)
{
    extern __shared__ unsigned char dyn[];
    unsigned long long* s_key = (unsigned long long*)(dyn + OFF_KEY);
    int*    s_cur  = (int*)(dyn + OFF_CUR);
    float4* s_pref = (float4*)(dyn + OFF_PREF);

    __shared__ int s_wsum[8];
    __shared__ int s_total, s_S, s_cutb, s_p1;

    const int bc   = blockIdx.x;
    const int b    = bc / NC;
    const int tid  = threadIdx.x;
    const int lane = tid & 31;
    const int wid  = tid >> 5;

    const float*  sc_row = scores + (size_t)bc * NN;
    const float4* bx_row = (const float4*)boxes + (size_t)b * NN;

    // ---- Phase 1: load scores into registers (coalesced) + zero histogram ----
    float ls[PER];
#pragma unroll
    for (int j = 0; j < PER; j++) {
        int i = j * NT + tid;
        ls[j] = (i < NN) ? sc_row[i] : 0.0f;
    }
#pragma unroll
    for (int j = 0; j < 4; j++) s_cur[tid * 4 + j] = 0;
    if (tid == 0) s_S = 0;
    __syncthreads();

    // histogram of kept scores (from registers)
#pragma unroll
    for (int j = 0; j < PER; j++) {
        if (ls[j] > 0.5f)
            atomicAdd(&s_cur[score_bucket_bits(__float_as_uint(ls[j]))], 1);
    }
    __syncthreads();

    // ---- Phase 2: exclusive prefix over HB buckets (4 contiguous/thread) ----
    int loc[4];
    int lsum = 0;
#pragma unroll
    for (int j = 0; j < 4; j++) { loc[j] = s_cur[tid * 4 + j]; lsum += loc[j]; }
    int pv = lsum;
#pragma unroll
    for (int o = 1; o < 32; o <<= 1) {
        int n = __shfl_up_sync(0xffffffffu, pv, o);
        if (lane >= o) pv += n;
    }
    if (lane == 31) s_wsum[wid] = pv;
    __syncthreads();
    if (tid == 0) {
        int acc = 0;
#pragma unroll
        for (int w = 0; w < 8; w++) { int x = s_wsum[w]; s_wsum[w] = acc; acc += x; }
    }
    __syncthreads();
    int bkbase = (pv - lsum) + s_wsum[wid];
#pragma unroll
    for (int j = 0; j < 4; j++) { s_cur[tid * 4 + j] = bkbase; bkbase += loc[j]; }
    if (tid == NT - 1) s_total = bkbase;
    __syncthreads();
    const int total = s_total;

    // ---- walk-selected-set registers (used by warp 0) ----
    float sx1[4], sy1[4], sx2[4], sy2[4], sar[4];
#pragma unroll
    for (int t = 0; t < 4; t++) { sx1[t]=0.f; sy1[t]=0.f; sx2[t]=0.f; sy2[t]=0.f; sar[t]=0.f; }

    int p0 = 0;        // absolute keys processed so far
    int bcur = 0;      // first unprocessed bucket
    while (true) {
        if (s_S >= MAXOUT || p0 >= total) break;      // uniform (post-barrier)

        // ---- cut bucket: smallest h >= bcur with start(h) >= p0 + KSEL ----
        if (tid == 0) s_cutb = HB;
        __syncthreads();
#pragma unroll
        for (int j = 0; j < 4; j++) {
            int h = tid * 4 + j;
            if (h >= bcur && s_cur[h] >= p0 + KSEL) atomicMin(&s_cutb, h);
        }
        __syncthreads();
        int cutb = s_cutb;
        if (tid == 0) s_p1 = (cutb < HB) ? s_cur[cutb] : total;
        __syncthreads();
        int p1 = s_p1;
        int bandn = p1 - p0;
        if (bandn > KCAP) bandn = KCAP;               // unreachable safety clamp

        // ---- scatter band keys FROM REGISTERS (no extra gmem pass) ----
#pragma unroll
        for (int j = 0; j < PER; j++) {
            if (ls[j] > 0.5f) {
                unsigned int bits = __float_as_uint(ls[j]);
                int bkt = score_bucket_bits(bits);
                if (bkt >= bcur && bkt < cutb) {
                    int pos = atomicAdd(&s_cur[bkt], 1) - p0;
                    if (pos < KCAP) {
                        int i = j * NT + tid;
                        s_key[pos] = ((unsigned long long)(~bits) << 32) | (unsigned int)i;
                    }
                }
            }
        }
        __syncthreads();

        // ---- per-bucket insertion sort, BAND BUCKETS ONLY (ascending u64) ----
        for (int h = bcur + tid; h < cutb; h += NT) {
            int s0 = ((h == bcur) ? p0 : s_cur[h - 1]) - p0;   // end(h-1)=start(h)
            int s1 = s_cur[h] - p0;
            if (s1 > KCAP) s1 = KCAP;
            for (int i2 = s0 + 1; i2 < s1; i2++) {
                unsigned long long key = s_key[i2];
                int j2 = i2 - 1;
                while (j2 >= s0 && s_key[j2] > key) { s_key[j2 + 1] = s_key[j2]; j2--; }
                s_key[j2 + 1] = key;
            }
        }
        __syncthreads();

        // ---- chunked prefetch + single-warp greedy walk over the band ----
        int chunk_start = 0;
        while (true) {
            int S0 = s_S;                             // uniform (post-barrier)
            if (chunk_start >= bandn || S0 >= MAXOUT) break;
            int chunk_end = chunk_start + PREF_K;
            if (chunk_end > bandn) chunk_end = bandn;

            int p = chunk_start + tid;
            if (p < chunk_end)
                s_pref[tid] = bx_row[(unsigned int)s_key[p]];   // low word = idx
            __syncthreads();

            if (wid == 0) {
                int S = S0;
                int n = chunk_end - chunk_start;
                float4 nb = s_pref[0];                 // software pipeline
                for (int q = 0; q < n && S < MAXOUT; ++q) {
                    float4 cb = nb;
                    if (q + 1 < n) nb = s_pref[q + 1]; // LDS off critical path
                    float ca = (cb.z - cb.x) * (cb.w - cb.y);
                    int tmax = S >> 5;                 // warp-uniform slot bound
                    int sup = 0;
#pragma unroll
                    for (int t = 0; t < 4; t++) {
                        if (t > tmax) break;
                        bool valid = (t * 32 + lane) < S;
                        float ix1 = fmaxf(sx1[t], cb.x);
                        float iy1 = fmaxf(sy1[t], cb.y);
                        float ix2 = fminf(sx2[t], cb.z);
                        float iy2 = fminf(sy2[t], cb.w);
                        float w   = fmaxf(ix2 - ix1, 0.f);
                        float h   = fmaxf(iy2 - iy1, 0.f);
                        float inter = w * h;
                        // Bit-exact reference compare (validated rel_err==0.0):
                        // suppress iff rn(inter / rn(rn(ca+sar)-inter)) > 0.5
                        //   <=> inter - 0.5*U > U*2^-25 (exact in deciding band)
                        float tt = ca + sar[t];
                        float U  = tt - inter;
                        float d  = inter - 0.5f * U;
                        float lo = U * 2.9802322387695312e-8f;
                        if (valid && d > lo) sup = 1;
                    }
                    if (__ballot_sync(0xffffffffu, sup)) continue;
                    if (lane == (S & 31)) {
                        int t = S >> 5;
                        if      (t == 0) { sx1[0]=cb.x; sy1[0]=cb.y; sx2[0]=cb.z; sy2[0]=cb.w; sar[0]=ca; }
                        else if (t == 1) { sx1[1]=cb.x; sy1[1]=cb.y; sx2[1]=cb.z; sy2[1]=cb.w; sar[1]=ca; }
                        else if (t == 2) { sx1[2]=cb.x; sy1[2]=cb.y; sx2[2]=cb.z; sy2[2]=cb.w; sar[2]=ca; }
                        else             { sx1[3]=cb.x; sy1[3]=cb.y; sx2[3]=cb.z; sy2[3]=cb.w; sar[3]=ca; }
                    }
                    if (lane == 0)
                        g_sel[bc * MAXOUT + S] = (int)(unsigned int)s_key[chunk_start + q];
                    S++;
                }
                if (lane == 0) s_S = S;
            }
            __syncthreads();
            chunk_start = chunk_end;
        }

        p0 = p1;
        bcur = cutb;
    }
    if (tid == 0) g_cnt[bc] = s_S;
}

// ---------------------------------------------------------------------------
// Kernel 2: exclusive prefix scan of the 1280 per-row counts (one tiny block)
// ---------------------------------------------------------------------------
__global__ __launch_bounds__(NT)
void scan_kernel()
{
    __shared__ int s_w[8];
    int tid = threadIdx.x, lane = tid & 31, wid = tid >> 5;
    int c[5];
    int sum = 0;
#pragma unroll
    for (int j = 0; j < 5; j++) { c[j] = g_cnt[tid * 5 + j]; sum += c[j]; }
    int v = sum;
#pragma unroll
    for (int o = 1; o < 32; o <<= 1) {
        int n = __shfl_up_sync(0xffffffffu, v, o);
        if (lane >= o) v += n;
    }
    if (lane == 31) s_w[wid] = v;
    __syncthreads();
    if (tid == 0) {
        int acc = 0;
#pragma unroll
        for (int w = 0; w < 8; w++) { int x = s_w[w]; s_w[w] = acc; acc += x; }
    }
    __syncthreads();
    int base = (v - sum) + s_w[wid];
#pragma unroll
    for (int j = 0; j < 5; j++) { g_off[tid * 5 + j] = base; base += c[j]; }
}

// ---------------------------------------------------------------------------
// Kernel 3: fused pack. Packed region [0, 3T) written only by the scatter;
// tail [3T, lim) only by the zero loop — disjoint. Triples as FLOAT values
// (output buffer is compared as float32; all values exact in fp32).
// ---------------------------------------------------------------------------
__global__ __launch_bounds__(NT)
void pack_kernel(float* __restrict__ out, int out_elems)
{
    int i = blockIdx.x * blockDim.x + threadIdx.x;   // over OUT_ROWS
    int lim = out_elems < OUT_ELEMS ? out_elems : OUT_ELEMS;
    int T = g_off[NBC - 1] + g_cnt[NBC - 1];         // total packed triples

    if (i < OUT_ROWS) {
        int bc = i / MAXOUT;
        int k  = i - bc * MAXOUT;
        if (k < g_cnt[bc]) {
            int d = g_off[bc] + k;
            if (3 * d + 2 < lim) {
                out[3 * d + 0] = (float)(bc / NC);
                out[3 * d + 1] = (float)(bc % NC);
                out[3 * d + 2] = (float)g_sel[i];
            }
        }
    }
    // tail zeros (grid-stride over [3T, lim))
    for (int z = 3 * T + i; z < lim; z += OUT_ROWS) out[z] = 0.0f;
}

// ---------------------------------------------------------------------------
extern "C" void kernel_launch(void* const* d_in, const int* in_sizes, int n_in,
                              void* d_out, int out_size)
{
    // Identify buffers by RELATIVE size: scores (6.4M elems) >> boxes (320k).
    const float* boxes  = (const float*)d_in[0];
    const float* scores = (const float*)d_in[1];
    if (n_in >= 2 && in_sizes[0] > in_sizes[1]) {
        scores = (const float*)d_in[0];
        boxes  = (const float*)d_in[1];
    }
    float* out = (float*)d_out;

    nms_kernel<<<NBC, NT, DYNSZ>>>(boxes, scores);   // 13.3KB dyn smem
    scan_kernel<<<1, NT>>>();
    pack_kernel<<<(OUT_ROWS + NT - 1) / NT, NT>>>(out, out_size);
}

// round 17
// speedup vs baseline: 1.6556x; 1.3888x over previous
#include <cuda_runtime.h>

// Problem constants (NonMaxSuppression: B=16, C=80, N=5000)
#define NB      16
#define NC      80
#define NN      5000
#define MAXOUT  100
#define NBC     (NB * NC)          // 1280
#define NT      256                // threads per CTA (select/fallback)
#define HB      1024               // counting-sort buckets (10 bits of ~score)
#define KSEL    512                // top-K band target (walk needs ~130)
#define KCAP    640                // key/box slots per row
#define WPB     4                  // walk warps per CTA (1 row per warp)
#define OUT_ROWS (NBC * MAXOUT)    // 128000
#define OUT_ELEMS (OUT_ROWS * 3)   // 384000

// Cross-kernel scratch (device globals: the sanctioned no-alloc scratch)
__device__ int    g_sel[OUT_ROWS];
__device__ int    g_cnt[NBC];
__device__ int    g_off[NBC];
__device__ int    g_need[NBC];     // row requires full fallback
__device__ int    g_bandn[NBC];    // sorted candidates exported for the row
__device__ int    g_total[NBC];    // total score>0.5 candidates in the row
__device__ float4 g_boxes[NBC * KCAP];  // sorted band boxes   (13.1 MB)
__device__ int    g_ids[NBC * KCAP];    // sorted band orig ids (3.3 MB)

// Bucket from score bits (score in (0.5,1) => bits in [0x3F000001,0x3F7FFFFF]).
// ~bits ascends where score descends; top 10 bits give the bucket. Clamped.
__device__ __forceinline__ int score_bucket_bits(unsigned int bits)
{
    int bkt = (int)((~bits) >> 13) - 0x60400;
    bkt = bkt < 0 ? 0 : (bkt > (HB - 1) ? (HB - 1) : bkt);
    return bkt;
}

// ---------------------------------------------------------------------------
// Kernel 1: SELECT. One CTA per row; all warps busy; no serial phase.
// Stages scores (float4), histograms, scans, scatters+sorts the top-512 band
// (u64 key = (~score_bits<<32)|idx; ascending == (score desc, idx asc) ==
// exact greedy order incl. ties), and exports the band's boxes+ids sorted.
// Pathological band overflow (> KCAP) defers the row to the exact fallback.
// ---------------------------------------------------------------------------
__global__ __launch_bounds__(NT)
void select_kernel(const float* __restrict__ boxes, const float* __restrict__ scores)
{
    __shared__ float stage[NN];                    // 20000 B
    __shared__ unsigned long long s_key[KCAP];     // 5120 B
    __shared__ int s_cur[HB];                      // 4096 B
    __shared__ int s_wsum[8];
    __shared__ int s_total, s_cutb, s_p1;

    const int bc   = blockIdx.x;
    const int b    = bc / NC;
    const int tid  = threadIdx.x;
    const int lane = tid & 31;
    const int wid  = tid >> 5;

    const float4* sc4    = (const float4*)(scores + (size_t)bc * NN);
    const float4* bx_row = (const float4*)boxes + (size_t)b * NN;

    // ---- stage scores (vectorized; NN/4 = 1250 float4 loads) + zero hist ----
    for (int i = tid; i < NN / 4; i += NT) ((float4*)stage)[i] = sc4[i];
#pragma unroll
    for (int j = 0; j < HB / NT; j++) s_cur[tid + j * NT] = 0;
    __syncthreads();

    // ---- histogram of kept scores ----
    for (int i = tid; i < NN; i += NT) {
        float s = stage[i];
        if (s > 0.5f)
            atomicAdd(&s_cur[score_bucket_bits(__float_as_uint(s))], 1);
    }
    __syncthreads();

    // ---- exclusive prefix over HB buckets (4 contiguous/thread) ----
    int loc[4];
    int lsum = 0;
#pragma unroll
    for (int j = 0; j < 4; j++) { loc[j] = s_cur[tid * 4 + j]; lsum += loc[j]; }
    int pv = lsum;
#pragma unroll
    for (int o = 1; o < 32; o <<= 1) {
        int n = __shfl_up_sync(0xffffffffu, pv, o);
        if (lane >= o) pv += n;
    }
    if (lane == 31) s_wsum[wid] = pv;
    __syncthreads();
    if (tid == 0) {
        int acc = 0;
#pragma unroll
        for (int w = 0; w < 8; w++) { int x = s_wsum[w]; s_wsum[w] = acc; acc += x; }
    }
    __syncthreads();
    int bkbase = (pv - lsum) + s_wsum[wid];
#pragma unroll
    for (int j = 0; j < 4; j++) { s_cur[tid * 4 + j] = bkbase; bkbase += loc[j]; }
    if (tid == NT - 1) s_total = bkbase;
    __syncthreads();
    const int total = s_total;

    // ---- cut bucket: smallest h with start(h) >= KSEL ----
    if (tid == 0) s_cutb = HB;
    __syncthreads();
#pragma unroll
    for (int j = 0; j < 4; j++) {
        int h = tid * 4 + j;
        if (s_cur[h] >= KSEL) atomicMin(&s_cutb, h);
    }
    __syncthreads();
    int cutb = s_cutb;
    if (tid == 0) s_p1 = (cutb < HB) ? s_cur[cutb] : total;
    __syncthreads();
    int bandn = s_p1;

    if (bandn > KCAP) {            // pathological overshoot: exact fallback path
        if (tid == 0) { g_need[bc] = 1; g_bandn[bc] = 0; g_total[bc] = total; }
        return;
    }

    // ---- scatter band keys (band = buckets [0, cutb), positions [0, bandn)) ----
    for (int i = tid; i < NN; i += NT) {
        float s = stage[i];
        if (s > 0.5f) {
            unsigned int bits = __float_as_uint(s);
            int bkt = score_bucket_bits(bits);
            if (bkt < cutb) {
                int pos = atomicAdd(&s_cur[bkt], 1);
                s_key[pos] = ((unsigned long long)(~bits) << 32) | (unsigned int)i;
            }
        }
    }
    __syncthreads();

    // ---- per-bucket insertion sort (ascending u64 = exact greedy order) ----
    for (int h = tid; h < cutb; h += NT) {
        int s0 = (h == 0) ? 0 : s_cur[h - 1];      // end(h-1) == start(h)
        int s1 = s_cur[h];
        for (int i2 = s0 + 1; i2 < s1; i2++) {
            unsigned long long key = s_key[i2];
            int j2 = i2 - 1;
            while (j2 >= s0 && s_key[j2] > key) { s_key[j2 + 1] = s_key[j2]; j2--; }
            s_key[j2 + 1] = key;
        }
    }
    __syncthreads();

    // ---- export sorted band boxes + ids (parallel gather, L2-resident) ----
    for (int i = tid; i < bandn; i += NT) {
        unsigned int id = (unsigned int)s_key[i];
        g_boxes[bc * KCAP + i] = bx_row[id];
        g_ids[bc * KCAP + i]   = (int)id;
    }
    if (tid == 0) { g_need[bc] = 0; g_bandn[bc] = bandn; g_total[bc] = total; }
}

// ---------------------------------------------------------------------------
// Kernel 2: WALK. One warp per row, WPB rows per CTA — all 1280 serial walks
// run concurrently. Boxes broadcast via __shfl (no smem, no block barriers).
// ---------------------------------------------------------------------------
__global__ __launch_bounds__(WPB * 32)
void walk_kernel()
{
    const int lane = threadIdx.x & 31;
    const int wid  = threadIdx.x >> 5;
    const int bc   = blockIdx.x * WPB + wid;
    if (bc >= NBC) return;
    if (g_need[bc]) return;                        // fallback row

    const int bandn = g_bandn[bc];
    const int total = g_total[bc];
    const float4* bxc = g_boxes + bc * KCAP;
    const int*    idc = g_ids   + bc * KCAP;

    float sx1[4], sy1[4], sx2[4], sy2[4], sar[4];
#pragma unroll
    for (int t = 0; t < 4; t++) { sx1[t]=0.f; sy1[t]=0.f; sx2[t]=0.f; sy2[t]=0.f; sar[t]=0.f; }

    int S = 0;
    for (int cs = 0; cs < bandn && S < MAXOUT; cs += 32) {
        int p = cs + lane;
        float4 nbx = make_float4(0.f, 0.f, 0.f, 0.f);
        int nid = 0;
        if (p < bandn) { nbx = bxc[p]; nid = idc[p]; }  // coalesced chunk load
        int n = bandn - cs; if (n > 32) n = 32;

        for (int q = 0; q < n && S < MAXOUT; q++) {
            float cx1 = __shfl_sync(0xffffffffu, nbx.x, q);
            float cy1 = __shfl_sync(0xffffffffu, nbx.y, q);
            float cx2 = __shfl_sync(0xffffffffu, nbx.z, q);
            float cy2 = __shfl_sync(0xffffffffu, nbx.w, q);
            int   cid = __shfl_sync(0xffffffffu, nid,  q);
            float ca  = (cx2 - cx1) * (cy2 - cy1);
            int tmax = S >> 5;                     // warp-uniform slot bound
            int sup = 0;
#pragma unroll
            for (int t = 0; t < 4; t++) {
                if (t > tmax) break;
                bool valid = (t * 32 + lane) < S;
                float ix1 = fmaxf(sx1[t], cx1);
                float iy1 = fmaxf(sy1[t], cy1);
                float ix2 = fminf(sx2[t], cx2);
                float iy2 = fminf(sy2[t], cy2);
                float w   = fmaxf(ix2 - ix1, 0.f);
                float h   = fmaxf(iy2 - iy1, 0.f);
                float inter = w * h;
                // Bit-exact reference compare (validated rel_err==0.0):
                // suppress iff rn(inter / rn(rn(ca+sar)-inter)) > 0.5
                //   <=> inter - 0.5*U > U*2^-25 (exact in the deciding band)
                float tt = ca + sar[t];
                float U  = tt - inter;
                float d  = inter - 0.5f * U;
                float lo = U * 2.9802322387695312e-8f;
                if (valid && d > lo) sup = 1;
            }
            if (__ballot_sync(0xffffffffu, sup)) continue;
            if (lane == (S & 31)) {
                int t = S >> 5;
                if      (t == 0) { sx1[0]=cx1; sy1[0]=cy1; sx2[0]=cx2; sy2[0]=cy2; sar[0]=ca; }
                else if (t == 1) { sx1[1]=cx1; sy1[1]=cy1; sx2[1]=cx2; sy2[1]=cy2; sar[1]=ca; }
                else if (t == 2) { sx1[2]=cx1; sy1[2]=cy1; sx2[2]=cx2; sy2[2]=cy2; sar[2]=ca; }
                else             { sx1[3]=cx1; sy1[3]=cy1; sx2[3]=cx2; sy2[3]=cy2; sar[3]=ca; }
            }
            if (lane == 0) g_sel[bc * MAXOUT + S] = cid;
            S++;
        }
    }
    if (S < MAXOUT && bandn < total) {
        if (lane == 0) g_need[bc] = 1;             // band insufficient: fallback
    } else {
        if (lane == 0) g_cnt[bc] = S;
    }
}

// ---------------------------------------------------------------------------
// Kernel 3: FALLBACK — full exact per-row NMS (R16-validated band loop) for
// rows flagged by select/walk. Never triggers on benign data (~3 us idle).
// ---------------------------------------------------------------------------
__global__ __launch_bounds__(NT)
void fallback_kernel(const float* __restrict__ boxes, const float* __restrict__ scores)
{
    const int bc = blockIdx.x;
    if (!g_need[bc]) return;

    __shared__ unsigned long long s_key[KCAP];
    __shared__ int s_cur[HB];
    __shared__ float4 s_pref[NT];
    __shared__ int s_wsum[8];
    __shared__ int s_total, s_S, s_cutb, s_p1;

    const int b    = bc / NC;
    const int tid  = threadIdx.x;
    const int lane = tid & 31;
    const int wid  = tid >> 5;

    const float*  sc_row = scores + (size_t)bc * NN;
    const float4* bx_row = (const float4*)boxes + (size_t)b * NN;

    float ls[20];
#pragma unroll
    for (int j = 0; j < 20; j++) {
        int i = j * NT + tid;
        ls[j] = (i < NN) ? sc_row[i] : 0.0f;
    }
#pragma unroll
    for (int j = 0; j < 4; j++) s_cur[tid * 4 + j] = 0;
    if (tid == 0) s_S = 0;
    __syncthreads();

#pragma unroll
    for (int j = 0; j < 20; j++) {
        if (ls[j] > 0.5f)
            atomicAdd(&s_cur[score_bucket_bits(__float_as_uint(ls[j]))], 1);
    }
    __syncthreads();

    int loc[4];
    int lsum = 0;
#pragma unroll
    for (int j = 0; j < 4; j++) { loc[j] = s_cur[tid * 4 + j]; lsum += loc[j]; }
    int pv = lsum;
#pragma unroll
    for (int o = 1; o < 32; o <<= 1) {
        int n = __shfl_up_sync(0xffffffffu, pv, o);
        if (lane >= o) pv += n;
    }
    if (lane == 31) s_wsum[wid] = pv;
    __syncthreads();
    if (tid == 0) {
        int acc = 0;
#pragma unroll
        for (int w = 0; w < 8; w++) { int x = s_wsum[w]; s_wsum[w] = acc; acc += x; }
    }
    __syncthreads();
    int bkbase = (pv - lsum) + s_wsum[wid];
#pragma unroll
    for (int j = 0; j < 4; j++) { s_cur[tid * 4 + j] = bkbase; bkbase += loc[j]; }
    if (tid == NT - 1) s_total = bkbase;
    __syncthreads();
    const int total = s_total;

    float sx1[4], sy1[4], sx2[4], sy2[4], sar[4];
#pragma unroll
    for (int t = 0; t < 4; t++) { sx1[t]=0.f; sy1[t]=0.f; sx2[t]=0.f; sy2[t]=0.f; sar[t]=0.f; }

    int p0 = 0, bcur = 0;
    while (true) {
        if (s_S >= MAXOUT || p0 >= total) break;

        if (tid == 0) s_cutb = HB;
        __syncthreads();
#pragma unroll
        for (int j = 0; j < 4; j++) {
            int h = tid * 4 + j;
            if (h >= bcur && s_cur[h] >= p0 + KSEL) atomicMin(&s_cutb, h);
        }
        __syncthreads();
        int cutb = s_cutb;
        if (tid == 0) s_p1 = (cutb < HB) ? s_cur[cutb] : total;
        __syncthreads();
        int p1 = s_p1;
        int bandn = p1 - p0;
        if (bandn > KCAP) bandn = KCAP;

#pragma unroll
        for (int j = 0; j < 20; j++) {
            if (ls[j] > 0.5f) {
                unsigned int bits = __float_as_uint(ls[j]);
                int bkt = score_bucket_bits(bits);
                if (bkt >= bcur && bkt < cutb) {
                    int pos = atomicAdd(&s_cur[bkt], 1) - p0;
                    if (pos < KCAP) {
                        int i = j * NT + tid;
                        s_key[pos] = ((unsigned long long)(~bits) << 32) | (unsigned int)i;
                    }
                }
            }
        }
        __syncthreads();

        for (int h = bcur + tid; h < cutb; h += NT) {
            int s0 = ((h == bcur) ? p0 : s_cur[h - 1]) - p0;
            int s1 = s_cur[h] - p0;
            if (s1 > KCAP) s1 = KCAP;
            for (int i2 = s0 + 1; i2 < s1; i2++) {
                unsigned long long key = s_key[i2];
                int j2 = i2 - 1;
                while (j2 >= s0 && s_key[j2] > key) { s_key[j2 + 1] = s_key[j2]; j2--; }
                s_key[j2 + 1] = key;
            }
        }
        __syncthreads();

        int chunk_start = 0;
        while (true) {
            int S0 = s_S;
            if (chunk_start >= bandn || S0 >= MAXOUT) break;
            int chunk_end = chunk_start + NT;
            if (chunk_end > bandn) chunk_end = bandn;

            int p = chunk_start + tid;
            if (p < chunk_end)
                s_pref[tid] = bx_row[(unsigned int)s_key[p]];
            __syncthreads();

            if (wid == 0) {
                int S = S0;
                int n = chunk_end - chunk_start;
                for (int q = 0; q < n && S < MAXOUT; ++q) {
                    float4 cb = s_pref[q];
                    float ca = (cb.z - cb.x) * (cb.w - cb.y);
                    int tmax = S >> 5;
                    int sup = 0;
#pragma unroll
                    for (int t = 0; t < 4; t++) {
                        if (t > tmax) break;
                        bool valid = (t * 32 + lane) < S;
                        float ix1 = fmaxf(sx1[t], cb.x);
                        float iy1 = fmaxf(sy1[t], cb.y);
                        float ix2 = fminf(sx2[t], cb.z);
                        float iy2 = fminf(sy2[t], cb.w);
                        float w   = fmaxf(ix2 - ix1, 0.f);
                        float h   = fmaxf(iy2 - iy1, 0.f);
                        float inter = w * h;
                        float tt = ca + sar[t];
                        float U  = tt - inter;
                        float d  = inter - 0.5f * U;
                        float lo = U * 2.9802322387695312e-8f;
                        if (valid && d > lo) sup = 1;
                    }
                    if (__ballot_sync(0xffffffffu, sup)) continue;
                    if (lane == (S & 31)) {
                        int t = S >> 5;
                        if      (t == 0) { sx1[0]=cb.x; sy1[0]=cb.y; sx2[0]=cb.z; sy2[0]=cb.w; sar[0]=ca; }
                        else if (t == 1) { sx1[1]=cb.x; sy1[1]=cb.y; sx2[1]=cb.z; sy2[1]=cb.w; sar[1]=ca; }
                        else if (t == 2) { sx1[2]=cb.x; sy1[2]=cb.y; sx2[2]=cb.z; sy2[2]=cb.w; sar[2]=ca; }
                        else             { sx1[3]=cb.x; sy1[3]=cb.y; sx2[3]=cb.z; sy2[3]=cb.w; sar[3]=ca; }
                    }
                    if (lane == 0)
                        g_sel[bc * MAXOUT + S] = (int)(unsigned int)s_key[chunk_start + q];
                    S++;
                }
                if (lane == 0) s_S = S;
            }
            __syncthreads();
            chunk_start = chunk_end;
        }

        p0 = p1;
        bcur = cutb;
    }
    if (tid == 0) g_cnt[bc] = s_S;
}

// ---------------------------------------------------------------------------
// Kernel 4: exclusive prefix scan of the 1280 per-row counts (one tiny block)
// ---------------------------------------------------------------------------
__global__ __launch_bounds__(NT)
void scan_kernel()
{
    __shared__ int s_w[8];
    int tid = threadIdx.x, lane = tid & 31, wid = tid >> 5;
    int c[5];
    int sum = 0;
#pragma unroll
    for (int j = 0; j < 5; j++) { c[j] = g_cnt[tid * 5 + j]; sum += c[j]; }
    int v = sum;
#pragma unroll
    for (int o = 1; o < 32; o <<= 1) {
        int n = __shfl_up_sync(0xffffffffu, v, o);
        if (lane >= o) v += n;
    }
    if (lane == 31) s_w[wid] = v;
    __syncthreads();
    if (tid == 0) {
        int acc = 0;
#pragma unroll
        for (int w = 0; w < 8; w++) { int x = s_w[w]; s_w[w] = acc; acc += x; }
    }
    __syncthreads();
    int base = (v - sum) + s_w[wid];
#pragma unroll
    for (int j = 0; j < 5; j++) { g_off[tid * 5 + j] = base; base += c[j]; }
}

// ---------------------------------------------------------------------------
// Kernel 5: fused pack — scatter packed (b,c,idx) triples as FLOAT values
// (output compared as float32; all values exact in fp32) + tail zeros.
// ---------------------------------------------------------------------------
__global__ __launch_bounds__(NT)
void pack_kernel(float* __restrict__ out, int out_elems)
{
    int i = blockIdx.x * blockDim.x + threadIdx.x;   // over OUT_ROWS
    int lim = out_elems < OUT_ELEMS ? out_elems : OUT_ELEMS;
    int T = g_off[NBC - 1] + g_cnt[NBC - 1];         // total packed triples

    if (i < OUT_ROWS) {
        int bc = i / MAXOUT;
        int k  = i - bc * MAXOUT;
        if (k < g_cnt[bc]) {
            int d = g_off[bc] + k;
            if (3 * d + 2 < lim) {
                out[3 * d + 0] = (float)(bc / NC);
                out[3 * d + 1] = (float)(bc % NC);
                out[3 * d + 2] = (float)g_sel[i];
            }
        }
    }
    for (int z = 3 * T + i; z < lim; z += OUT_ROWS) out[z] = 0.0f;
}

// ---------------------------------------------------------------------------
extern "C" void kernel_launch(void* const* d_in, const int* in_sizes, int n_in,
                              void* d_out, int out_size)
{
    // Identify buffers by RELATIVE size: scores (6.4M elems) >> boxes (320k).
    const float* boxes  = (const float*)d_in[0];
    const float* scores = (const float*)d_in[1];
    if (n_in >= 2 && in_sizes[0] > in_sizes[1]) {
        scores = (const float*)d_in[0];
        boxes  = (const float*)d_in[1];
    }
    float* out = (float*)d_out;

    select_kernel<<<NBC, NT>>>(boxes, scores);
    walk_kernel<<<(NBC + WPB - 1) / WPB, WPB * 32>>>();
    fallback_kernel<<<NBC, NT>>>(boxes, scores);
    scan_kernel<<<1, NT>>>();
    pack_kernel<<<(OUT_ROWS + NT - 1) / NT, NT>>>(out, out_size);
}